// round 6
// baseline (speedup 1.0000x reference)
#include <cuda_runtime.h>
#include <cuda_bf16.h>
#include <math.h>
#include <stdint.h>

#define V  50257
#define H  1024
#define L  2048
#define ML 2048
#define NSG 256   // score_g partial blocks

typedef unsigned long long ull;

// ---------------- scratch (device globals; no allocations allowed) ----------------
__device__ float g_attn_logits[ML];
__device__ float g_attn_applied[H];
__device__ float g_rnn_in[H];
__device__ float g_gi[3 * H];
__device__ float g_gh[3 * H];
__device__ float g_hnew[H];
__device__ float g_score_g[V];
__device__ float g_score_c[L];
__device__ float g_sgmax[NSG];
__device__ float g_sgsum[NSG];
__device__ float g_smax;
__device__ float g_sinv;
// split-bf16 copies of E and W_copy
__device__ __nv_bfloat16 g_Eh[L * H];
__device__ __nv_bfloat16 g_El[L * H];
__device__ __nv_bfloat16 g_Wh[H * H];
__device__ __nv_bfloat16 g_Wl[H * H];

// ---------------- helpers ----------------
__device__ __forceinline__ float block_reduce_max(float v, float* sred) {
    #pragma unroll
    for (int o = 16; o; o >>= 1) v = fmaxf(v, __shfl_xor_sync(0xffffffffu, v, o));
    int w = threadIdx.x >> 5;
    if ((threadIdx.x & 31) == 0) sred[w] = v;
    __syncthreads();
    int nw = (blockDim.x + 31) >> 5;
    if (threadIdx.x < 32) {
        float x = (threadIdx.x < nw) ? sred[threadIdx.x] : -1e30f;
        #pragma unroll
        for (int o = 16; o; o >>= 1) x = fmaxf(x, __shfl_xor_sync(0xffffffffu, x, o));
        if (threadIdx.x == 0) sred[0] = x;
    }
    __syncthreads();
    float r = sred[0];
    __syncthreads();
    return r;
}

__device__ __forceinline__ float block_reduce_sum(float v, float* sred) {
    #pragma unroll
    for (int o = 16; o; o >>= 1) v += __shfl_xor_sync(0xffffffffu, v, o);
    int w = threadIdx.x >> 5;
    if ((threadIdx.x & 31) == 0) sred[w] = v;
    __syncthreads();
    int nw = (blockDim.x + 31) >> 5;
    if (threadIdx.x < 32) {
        float x = (threadIdx.x < nw) ? sred[threadIdx.x] : 0.f;
        #pragma unroll
        for (int o = 16; o; o >>= 1) x += __shfl_xor_sync(0xffffffffu, x, o);
        if (threadIdx.x == 0) sred[0] = x;
    }
    __syncthreads();
    float r = sred[0];
    __syncthreads();
    return r;
}

__device__ __forceinline__ float warp_reduce_sum(float v) {
    #pragma unroll
    for (int o = 16; o; o >>= 1) v += __shfl_down_sync(0xffffffffu, v, o);
    return v;
}

__device__ __forceinline__ uint32_t smem_u32(const void* p) {
    return (uint32_t)__cvta_generic_to_shared(p);
}
__device__ __forceinline__ void ldsm_x4(uint32_t* r, uint32_t addr) {
    asm volatile("ldmatrix.sync.aligned.m8n8.x4.shared.b16 {%0,%1,%2,%3}, [%4];"
        : "=r"(r[0]), "=r"(r[1]), "=r"(r[2]), "=r"(r[3]) : "r"(addr));
}
__device__ __forceinline__ void ldsm_x2(uint32_t* r, uint32_t addr) {
    asm volatile("ldmatrix.sync.aligned.m8n8.x2.shared.b16 {%0,%1}, [%2];"
        : "=r"(r[0]), "=r"(r[1]) : "r"(addr));
}
__device__ __forceinline__ void mma_bf16(float* d, const uint32_t* a, const uint32_t* b) {
    asm volatile("mma.sync.aligned.m16n8k16.row.col.f32.bf16.bf16.f32 "
        "{%0,%1,%2,%3}, {%4,%5,%6,%7}, {%8,%9}, {%0,%1,%2,%3};"
        : "+f"(d[0]), "+f"(d[1]), "+f"(d[2]), "+f"(d[3])
        : "r"(a[0]), "r"(a[1]), "r"(a[2]), "r"(a[3]), "r"(b[0]), "r"(b[1]));
}
__device__ __forceinline__ float trunc_hi(float x) {
    return __uint_as_float(__float_as_uint(x) & 0xffff0000u);
}

// ---------------- kernels ----------------

__global__ void k_init() {
    int i = blockIdx.x * blockDim.x + threadIdx.x;
    if (i < H) g_attn_applied[i] = 0.f;
    if (i < L) g_score_c[i] = 0.f;
}

// split E and W_copy into bf16 hi/lo
__global__ void k_split(const float* __restrict__ E, const float* __restrict__ W) {
    const int NE4 = (L * H) / 4;
    const int NW4 = (H * H) / 4;
    int i = blockIdx.x * blockDim.x + threadIdx.x;
    if (i >= NE4 + NW4) return;
    const float4* src;
    __nv_bfloat162 *dh, *dl;
    int b;
    if (i < NE4) {
        src = (const float4*)E; dh = (__nv_bfloat162*)g_Eh; dl = (__nv_bfloat162*)g_El; b = i;
    } else {
        src = (const float4*)W; dh = (__nv_bfloat162*)g_Wh; dl = (__nv_bfloat162*)g_Wl; b = i - NE4;
    }
    float4 v = src[b];
    float hx = trunc_hi(v.x), hy = trunc_hi(v.y), hz = trunc_hi(v.z), hw = trunc_hi(v.w);
    dh[2 * b + 0] = __floats2bfloat162_rn(hx, hy);
    dh[2 * b + 1] = __floats2bfloat162_rn(hz, hw);
    dl[2 * b + 0] = __floats2bfloat162_rn(v.x - hx, v.y - hy);
    dl[2 * b + 1] = __floats2bfloat162_rn(v.z - hz, v.w - hw);
}

// attn_logits[m] = [emb0, h0] . W_attn_w[m] + b_attn_w[m]
__global__ void k_attn_logits(const int* __restrict__ din_p,
                              const float* __restrict__ emb,
                              const float* __restrict__ h0,
                              const float* __restrict__ Ww,
                              const float* __restrict__ bw) {
    int row  = (blockIdx.x * blockDim.x + threadIdx.x) >> 5;
    int lane = threadIdx.x & 31;
    if (row >= ML) return;
    const float4* w4 = (const float4*)(Ww + (size_t)row * (2 * H));
    const float4* e4 = (const float4*)(emb + (size_t)din_p[0] * H);
    const float4* h4 = (const float4*)h0;
    float acc = 0.f;
    #pragma unroll
    for (int q = lane; q < 256; q += 32) {
        float4 a = w4[q]; float4 x = e4[q];
        acc += a.x * x.x + a.y * x.y + a.z * x.z + a.w * x.w;
    }
    #pragma unroll
    for (int q = lane; q < 256; q += 32) {
        float4 a = w4[256 + q]; float4 x = h4[q];
        acc += a.x * x.x + a.y * x.y + a.z * x.z + a.w * x.w;
    }
    acc = warp_reduce_sum(acc);
    if (lane == 0) g_attn_logits[row] = acc + bw[row];
}

// fused softmax(ML) + attn_applied
__global__ void k_attn_applied(const float* __restrict__ E) {
    __shared__ float sred[32];
    __shared__ float w[16];
    int t = threadIdx.x;
    float a = g_attn_logits[t];
    float b = g_attn_logits[t + 1024];
    float m = block_reduce_max(fmaxf(a, b), sred);
    float s = block_reduce_sum(expf(a - m) + expf(b - m), sred);
    float inv = 1.f / s;
    int r0 = blockIdx.x * 16;
    if (t < 16) w[t] = expf(g_attn_logits[r0 + t] - m) * inv;
    __syncthreads();
    float acc = 0.f;
    #pragma unroll
    for (int i = 0; i < 16; i++)
        acc += w[i] * E[(size_t)(r0 + i) * H + t];
    atomicAdd(&g_attn_applied[t], acc);
}

// rnn_in[j] = relu([emb0, attn_applied] . W_attn_u[j] + b_attn_u[j])
__global__ void k_rnn_in(const int* __restrict__ din_p,
                         const float* __restrict__ emb,
                         const float* __restrict__ Wu,
                         const float* __restrict__ bu) {
    int row  = (blockIdx.x * blockDim.x + threadIdx.x) >> 5;
    int lane = threadIdx.x & 31;
    if (row >= H) return;
    const float4* w4 = (const float4*)(Wu + (size_t)row * (2 * H));
    const float4* e4 = (const float4*)(emb + (size_t)din_p[0] * H);
    const float4* a4 = (const float4*)g_attn_applied;
    float acc = 0.f;
    #pragma unroll
    for (int q = lane; q < 256; q += 32) {
        float4 a = w4[q]; float4 x = e4[q];
        acc += a.x * x.x + a.y * x.y + a.z * x.z + a.w * x.w;
    }
    #pragma unroll
    for (int q = lane; q < 256; q += 32) {
        float4 a = w4[256 + q]; float4 x = a4[q];
        acc += a.x * x.x + a.y * x.y + a.z * x.z + a.w * x.w;
    }
    acc = warp_reduce_sum(acc);
    if (lane == 0) g_rnn_in[row] = fmaxf(acc + bu[row], 0.f);
}

// gh = W_hh @ h0 + b_hh  (forked early)
__global__ void k_gh(const float* __restrict__ Whh, const float* __restrict__ bhh,
                     const float* __restrict__ h0) {
    int g    = (blockIdx.x * blockDim.x + threadIdx.x) >> 5;
    int lane = threadIdx.x & 31;
    if (g >= 3 * H) return;
    const float4* w4 = (const float4*)(Whh + (size_t)g * H);
    const float4* x4 = (const float4*)h0;
    float acc = 0.f;
    #pragma unroll
    for (int q = lane; q < 256; q += 32) {
        float4 a = w4[q]; float4 x = x4[q];
        acc += a.x * x.x + a.y * x.y + a.z * x.z + a.w * x.w;
    }
    acc = warp_reduce_sum(acc);
    if (lane == 0) g_gh[g] = acc + bhh[g];
}

// gi = W_ih @ rnn_in + b_ih
__global__ void k_gi(const float* __restrict__ Wih, const float* __restrict__ bih) {
    int g    = (blockIdx.x * blockDim.x + threadIdx.x) >> 5;
    int lane = threadIdx.x & 31;
    if (g >= 3 * H) return;
    const float4* w4 = (const float4*)(Wih + (size_t)g * H);
    const float4* x4 = (const float4*)g_rnn_in;
    float acc = 0.f;
    #pragma unroll
    for (int q = lane; q < 256; q += 32) {
        float4 a = w4[q]; float4 x = x4[q];
        acc += a.x * x.x + a.y * x.y + a.z * x.z + a.w * x.w;
    }
    acc = warp_reduce_sum(acc);
    if (lane == 0) g_gi[g] = acc + bih[g];
}

// GRU combine; writes h_new and final_hidden
__global__ void k_gru(const float* __restrict__ h0, float* __restrict__ out) {
    int t = threadIdx.x;
    float r = 1.f / (1.f + expf(-(g_gi[t] + g_gh[t])));
    float z = 1.f / (1.f + expf(-(g_gi[H + t] + g_gh[H + t])));
    float n = tanhf(g_gi[2 * H + t] + r * g_gh[2 * H + t]);
    float h = (1.f - z) * n + z * h0[t];
    g_hnew[t] = h;
    out[V + t] = h;
}

// score_g GEMV with fused per-block softmax partials.
// NSG blocks x 1024 threads (32 warps). Warp gw handles rows gw, gw+8192, ...
__global__ __launch_bounds__(1024) void k_score_g(const float* __restrict__ Wg,
                                                  const float* __restrict__ bg) {
    __shared__ float sm[32], ss[32];
    int wid  = threadIdx.x >> 5;
    int lane = threadIdx.x & 31;
    int gw = blockIdx.x * 32 + wid;
    const float4* h4 = (const float4*)g_hnew;
    float lm = -1e30f, lsum = 0.f;
    for (int row = gw; row < V; row += NSG * 32) {
        const float4* w4 = (const float4*)(Wg + (size_t)row * H);
        float acc = 0.f;
        #pragma unroll
        for (int q = 0; q < 8; q++) {
            float4 a = w4[q * 32 + lane]; float4 x = h4[q * 32 + lane];
            acc += a.x * x.x + a.y * x.y + a.z * x.z + a.w * x.w;
        }
        acc = warp_reduce_sum(acc);
        if (lane == 0) {
            float sc = acc + bg[row];
            g_score_g[row] = sc;
            float nm = fmaxf(lm, sc);
            lsum = lsum * expf(lm - nm) + expf(sc - nm);
            lm = nm;
        }
    }
    if (lane == 0) { sm[wid] = lm; ss[wid] = lsum; }
    __syncthreads();
    if (threadIdx.x < 32) {
        float m = sm[threadIdx.x], s = ss[threadIdx.x];
        #pragma unroll
        for (int o = 16; o; o >>= 1) {
            float mo = __shfl_xor_sync(0xffffffffu, m, o);
            float so = __shfl_xor_sync(0xffffffffu, s, o);
            float nm = fmaxf(m, mo);
            s = s * expf(m - nm) + so * expf(mo - nm);
            m = nm;
        }
        if (threadIdx.x == 0) { g_sgmax[blockIdx.x] = m; g_sgsum[blockIdx.x] = s; }
    }
}

// score_c via split-bf16 tensor-core GEMM (R4 proven version: static smem).
#define SAB 40
__global__ __launch_bounds__(256) void k_score_c_mma(
    const float* __restrict__ bias, const float* __restrict__ h0) {
    __shared__ __nv_bfloat16 sAh[128 * SAB], sAl[128 * SAB];
    __shared__ __nv_bfloat16 sBh[128 * SAB], sBl[128 * SAB];
    int tid  = threadIdx.x;
    int lane = tid & 31;
    int wid  = tid >> 5;
    int wm   = wid >> 2;
    int wn   = wid & 3;
    int rowBase = blockIdx.y * 128;
    int colBase = blockIdx.x * 128;

    float acc[4][4][4];
    #pragma unroll
    for (int mf = 0; mf < 4; mf++)
        #pragma unroll
        for (int nf = 0; nf < 4; nf++)
            #pragma unroll
            for (int r = 0; r < 4; r++) acc[mf][nf][r] = 0.f;

    int lr   = tid >> 2;
    int lseg = tid & 3;

    uint4 vah[2], valo[2], vbh[2], vblo[2];
    #pragma unroll
    for (int p = 0; p < 2; p++) {
        int ra = lr + p * 64;
        size_t offA = ((size_t)(rowBase + ra) << 10) + lseg * 8;
        size_t offB = ((size_t)(colBase + ra) << 10) + lseg * 8;
        vah[p]  = *(const uint4*)(g_Eh + offA);
        valo[p] = *(const uint4*)(g_El + offA);
        vbh[p]  = *(const uint4*)(g_Wh + offB);
        vblo[p] = *(const uint4*)(g_Wl + offB);
    }

    for (int kt = 0; kt < 1024; kt += 32) {
        #pragma unroll
        for (int p = 0; p < 2; p++) {
            int ra = lr + p * 64;
            *(uint4*)&sAh[ra * SAB + lseg * 8] = vah[p];
            *(uint4*)&sAl[ra * SAB + lseg * 8] = valo[p];
            *(uint4*)&sBh[ra * SAB + lseg * 8] = vbh[p];
            *(uint4*)&sBl[ra * SAB + lseg * 8] = vblo[p];
        }
        __syncthreads();
        if (kt + 32 < 1024) {
            #pragma unroll
            for (int p = 0; p < 2; p++) {
                int ra = lr + p * 64;
                size_t offA = ((size_t)(rowBase + ra) << 10) + kt + 32 + lseg * 8;
                size_t offB = ((size_t)(colBase + ra) << 10) + kt + 32 + lseg * 8;
                vah[p]  = *(const uint4*)(g_Eh + offA);
                valo[p] = *(const uint4*)(g_El + offA);
                vbh[p]  = *(const uint4*)(g_Wh + offB);
                vblo[p] = *(const uint4*)(g_Wl + offB);
            }
        }
        #pragma unroll
        for (int ks = 0; ks < 2; ks++) {
            int kk = ks * 16;
            uint32_t ah[4][4], al[4][4], bh[4][2], bl[4][2];
            int arow = wm * 64 + (lane & 15);
            int akc  = kk + ((lane >> 4) & 1) * 8;
            #pragma unroll
            for (int mf = 0; mf < 4; mf++) {
                ldsm_x4(ah[mf], smem_u32(&sAh[(arow + mf * 16) * SAB + akc]));
                ldsm_x4(al[mf], smem_u32(&sAl[(arow + mf * 16) * SAB + akc]));
            }
            int brow = wn * 32 + (lane & 7);
            int bkc  = kk + ((lane >> 3) & 1) * 8;
            #pragma unroll
            for (int nf = 0; nf < 4; nf++) {
                ldsm_x2(bh[nf], smem_u32(&sBh[(brow + nf * 8) * SAB + bkc]));
                ldsm_x2(bl[nf], smem_u32(&sBl[(brow + nf * 8) * SAB + bkc]));
            }
            #pragma unroll
            for (int mf = 0; mf < 4; mf++)
                #pragma unroll
                for (int nf = 0; nf < 4; nf++) {
                    mma_bf16(acc[mf][nf], ah[mf], bh[nf]);
                    mma_bf16(acc[mf][nf], ah[mf], bl[nf]);
                    mma_bf16(acc[mf][nf], al[mf], bh[nf]);
                }
        }
        __syncthreads();
    }

    int g   = lane >> 2;
    int tig = lane & 3;
    float bj[4][2], hj[4][2];
    #pragma unroll
    for (int nf = 0; nf < 4; nf++) {
        int j0 = colBase + wn * 32 + nf * 8 + tig * 2;
        bj[nf][0] = bias[j0];     bj[nf][1] = bias[j0 + 1];
        hj[nf][0] = h0[j0];       hj[nf][1] = h0[j0 + 1];
    }
    #pragma unroll
    for (int mf = 0; mf < 4; mf++) {
        float s0 = 0.f, s1 = 0.f;
        #pragma unroll
        for (int nf = 0; nf < 4; nf++) {
            s0 += tanhf(acc[mf][nf][0] + bj[nf][0]) * hj[nf][0]
                + tanhf(acc[mf][nf][1] + bj[nf][1]) * hj[nf][1];
            s1 += tanhf(acc[mf][nf][2] + bj[nf][0]) * hj[nf][0]
                + tanhf(acc[mf][nf][3] + bj[nf][1]) * hj[nf][1];
        }
        s0 += __shfl_xor_sync(0xffffffffu, s0, 1);
        s0 += __shfl_xor_sync(0xffffffffu, s0, 2);
        s1 += __shfl_xor_sync(0xffffffffu, s1, 1);
        s1 += __shfl_xor_sync(0xffffffffu, s1, 2);
        if (tig == 0) {
            int r = rowBase + wm * 64 + mf * 16 + g;
            atomicAdd(&g_score_c[r], s0);
            atomicAdd(&g_score_c[r + 8], s1);
        }
    }
}

// fused finisher: combine score_g partials + score_c -> (M, 1/S); compute final_weights.
__global__ __launch_bounds__(1024) void k_redfin_fw(const int* __restrict__ iv,
                                                    const int* __restrict__ din_p,
                                                    const float* __restrict__ E,
                                                    float* __restrict__ out) {
    __shared__ float sred[32];
    __shared__ int s_n;
    __shared__ int s_idx[L];
    __shared__ float s_pc[L];
    int t = threadIdx.x;
    float c0 = g_score_c[t];
    float c1 = g_score_c[t + 1024];
    float m = fmaxf(c0, c1);
    if (t < NSG) m = fmaxf(m, g_sgmax[t]);
    m = block_reduce_max(m, sred);
    float s = expf(c0 - m) + expf(c1 - m);
    if (t < NSG) s += g_sgsum[t] * expf(g_sgmax[t] - m);
    s = block_reduce_sum(s, sred);
    float sinv = 1.f / s;
    if (t == 0) { g_smax = m; g_sinv = sinv; s_n = 0; }
    __syncthreads();
    int din = din_p[0];
    if (iv[t] == din) {
        int p = atomicAdd(&s_n, 1);
        s_idx[p] = t; s_pc[p] = expf(c0 - m) * sinv;
    }
    if (iv[t + 1024] == din) {
        int p = atomicAdd(&s_n, 1);
        s_idx[p] = t + 1024; s_pc[p] = expf(c1 - m) * sinv;
    }
    __syncthreads();
    int n = s_n;
    float acc = 0.f;
    for (int p = 0; p < n; p++)
        acc += s_pc[p] * E[(size_t)s_idx[p] * H + t];
    out[V + H + t] = acc;   // final_weights (exact zero when no matches)
}

// final_output[v] = prob_g[v]
__global__ void k_out_g(float* __restrict__ out) {
    int i = blockIdx.x * blockDim.x + threadIdx.x;
    if (i >= V) return;
    out[i] = expf(g_score_g[i] - g_smax) * g_sinv;
}

// prob_c scatter-add (after out_g's plain stores)
__global__ void k_out_c(const int* __restrict__ iv, float* __restrict__ out) {
    int i = blockIdx.x * blockDim.x + threadIdx.x;
    if (i >= L) return;
    float pc = expf(g_score_c[i] - g_smax) * g_sinv;
    atomicAdd(&out[iv[i]], pc);
}

// ---------------- launcher ----------------
extern "C" void kernel_launch(void* const* d_in, const int* in_sizes, int n_in,
                              void* d_out, int out_size) {
    const int*   din  = (const int*)d_in[0];
    const float* h0   = (const float*)d_in[1];
    const float* E    = (const float*)d_in[2];
    const int*   iv   = (const int*)d_in[3];
    const float* emb  = (const float*)d_in[4];
    const float* Ww   = (const float*)d_in[5];
    const float* bw   = (const float*)d_in[6];
    const float* Wu   = (const float*)d_in[7];
    const float* bu   = (const float*)d_in[8];
    const float* Wih  = (const float*)d_in[9];
    const float* bih  = (const float*)d_in[10];
    const float* Whh  = (const float*)d_in[11];
    const float* bhh  = (const float*)d_in[12];
    const float* Wc   = (const float*)d_in[13];
    const float* bc   = (const float*)d_in[14];
    const float* Wg   = (const float*)d_in[15];
    const float* bg   = (const float*)d_in[16];
    float* out = (float*)d_out;

    static cudaStream_t s2 = nullptr, s3 = nullptr;
    static cudaEvent_t evF0 = nullptr, evF1 = nullptr, evGh = nullptr, evJoin = nullptr;
    if (s2 == nullptr) {
        cudaStreamCreateWithFlags(&s2, cudaStreamNonBlocking);
        cudaStreamCreateWithFlags(&s3, cudaStreamNonBlocking);
        cudaEventCreateWithFlags(&evF0, cudaEventDisableTiming);
        cudaEventCreateWithFlags(&evF1, cudaEventDisableTiming);
        cudaEventCreateWithFlags(&evGh, cudaEventDisableTiming);
        cudaEventCreateWithFlags(&evJoin, cudaEventDisableTiming);
    }

    // fork gh (input-only deps) onto s3 immediately
    cudaEventRecord(evF0, 0);
    cudaStreamWaitEvent(s3, evF0, 0);
    k_gh<<<(3 * H * 32) / 256, 256, 0, s3>>>(Whh, bhh, h0);
    cudaEventRecord(evGh, s3);

    k_init<<<8, 256>>>();

    // fork score_c pipeline onto s2 (after init: MMA epilogue atomicAdds to g_score_c)
    cudaEventRecord(evF1, 0);
    cudaStreamWaitEvent(s2, evF1, 0);
    k_split<<<((L * H + H * H) / 4 + 255) / 256, 256, 0, s2>>>(E, Wc);
    {
        dim3 grid(H / 128, L / 128);
        k_score_c_mma<<<grid, 256, 0, s2>>>(bc, h0);
    }
    cudaEventRecord(evJoin, s2);

    // main chain
    k_attn_logits<<<(ML * 32) / 256, 256>>>(din, emb, h0, Ww, bw);
    k_attn_applied<<<128, 1024>>>(E);
    k_rnn_in<<<(H * 32) / 256, 256>>>(din, emb, Wu, bu);
    k_gi<<<(3 * H * 32) / 256, 256>>>(Wih, bih);
    cudaStreamWaitEvent(0, evGh, 0);
    k_gru<<<1, 1024>>>(h0, out);
    k_score_g<<<NSG, 1024>>>(Wg, bg);

    // join + fused tail
    cudaStreamWaitEvent(0, evJoin, 0);
    k_redfin_fw<<<1, 1024>>>(iv, din, E, out);
    k_out_g<<<(V + 255) / 256, 256>>>(out);
    k_out_c<<<L / 256, 256>>>(iv, out);
}

// round 7
// speedup vs baseline: 1.0659x; 1.0659x over previous
#include <cuda_runtime.h>
#include <cuda_bf16.h>
#include <math.h>
#include <stdint.h>

#define V  50257
#define H  1024
#define L  2048
#define ML 2048
#define NRED 52

typedef unsigned long long ull;

// ---------------- scratch (device globals; no allocations allowed) ----------------
__device__ float g_attn_logits[ML];
__device__ float g_attn_applied[H];
__device__ float g_rnn_in[H];
__device__ float g_gi[3 * H];
__device__ float g_gh[3 * H];
__device__ float g_hnew[H];
__device__ float g_score_g[V];
__device__ float g_score_c[L];
__device__ float g_bmax[NRED];
__device__ float g_bsum[NRED];
__device__ float g_smax;
__device__ float g_sinv;

// ---------------- helpers ----------------
__device__ __forceinline__ float block_reduce_max(float v, float* sred) {
    #pragma unroll
    for (int o = 16; o; o >>= 1) v = fmaxf(v, __shfl_xor_sync(0xffffffffu, v, o));
    int w = threadIdx.x >> 5;
    if ((threadIdx.x & 31) == 0) sred[w] = v;
    __syncthreads();
    int nw = (blockDim.x + 31) >> 5;
    if (threadIdx.x < 32) {
        float x = (threadIdx.x < nw) ? sred[threadIdx.x] : -1e30f;
        #pragma unroll
        for (int o = 16; o; o >>= 1) x = fmaxf(x, __shfl_xor_sync(0xffffffffu, x, o));
        if (threadIdx.x == 0) sred[0] = x;
    }
    __syncthreads();
    float r = sred[0];
    __syncthreads();
    return r;
}

__device__ __forceinline__ float block_reduce_sum(float v, float* sred) {
    #pragma unroll
    for (int o = 16; o; o >>= 1) v += __shfl_xor_sync(0xffffffffu, v, o);
    int w = threadIdx.x >> 5;
    if ((threadIdx.x & 31) == 0) sred[w] = v;
    __syncthreads();
    int nw = (blockDim.x + 31) >> 5;
    if (threadIdx.x < 32) {
        float x = (threadIdx.x < nw) ? sred[threadIdx.x] : 0.f;
        #pragma unroll
        for (int o = 16; o; o >>= 1) x += __shfl_xor_sync(0xffffffffu, x, o);
        if (threadIdx.x == 0) sred[0] = x;
    }
    __syncthreads();
    float r = sred[0];
    __syncthreads();
    return r;
}

__device__ __forceinline__ float warp_reduce_sum(float v) {
    #pragma unroll
    for (int o = 16; o; o >>= 1) v += __shfl_down_sync(0xffffffffu, v, o);
    return v;
}

__device__ __forceinline__ uint32_t smem_u32(const void* p) {
    return (uint32_t)__cvta_generic_to_shared(p);
}
__device__ __forceinline__ void ldsm_x4(uint32_t* r, uint32_t addr) {
    asm volatile("ldmatrix.sync.aligned.m8n8.x4.shared.b16 {%0,%1,%2,%3}, [%4];"
        : "=r"(r[0]), "=r"(r[1]), "=r"(r[2]), "=r"(r[3]) : "r"(addr));
}
__device__ __forceinline__ void mma_bf16(float* d, const uint32_t* a, uint32_t b0, uint32_t b1) {
    asm volatile("mma.sync.aligned.m16n8k16.row.col.f32.bf16.bf16.f32 "
        "{%0,%1,%2,%3}, {%4,%5,%6,%7}, {%8,%9}, {%0,%1,%2,%3};"
        : "+f"(d[0]), "+f"(d[1]), "+f"(d[2]), "+f"(d[3])
        : "r"(a[0]), "r"(a[1]), "r"(a[2]), "r"(a[3]), "r"(b0), "r"(b1));
}
__device__ __forceinline__ float trunc_hi(float x) {
    return __uint_as_float(__float_as_uint(x) & 0xffff0000u);
}
// pack 8 fp32 (two float4) into 8 bf16 (uint4): hi parts
__device__ __forceinline__ uint4 pack_hi8(float4 a, float4 b) {
    __nv_bfloat162 p0 = __floats2bfloat162_rn(trunc_hi(a.x), trunc_hi(a.y));
    __nv_bfloat162 p1 = __floats2bfloat162_rn(trunc_hi(a.z), trunc_hi(a.w));
    __nv_bfloat162 p2 = __floats2bfloat162_rn(trunc_hi(b.x), trunc_hi(b.y));
    __nv_bfloat162 p3 = __floats2bfloat162_rn(trunc_hi(b.z), trunc_hi(b.w));
    uint4 r;
    r.x = *(uint32_t*)&p0; r.y = *(uint32_t*)&p1;
    r.z = *(uint32_t*)&p2; r.w = *(uint32_t*)&p3;
    return r;
}
// pack lo residuals
__device__ __forceinline__ uint4 pack_lo8(float4 a, float4 b) {
    __nv_bfloat162 p0 = __floats2bfloat162_rn(a.x - trunc_hi(a.x), a.y - trunc_hi(a.y));
    __nv_bfloat162 p1 = __floats2bfloat162_rn(a.z - trunc_hi(a.z), a.w - trunc_hi(a.w));
    __nv_bfloat162 p2 = __floats2bfloat162_rn(b.x - trunc_hi(b.x), b.y - trunc_hi(b.y));
    __nv_bfloat162 p3 = __floats2bfloat162_rn(b.z - trunc_hi(b.z), b.w - trunc_hi(b.w));
    uint4 r;
    r.x = *(uint32_t*)&p0; r.y = *(uint32_t*)&p1;
    r.z = *(uint32_t*)&p2; r.w = *(uint32_t*)&p3;
    return r;
}

// ---------------- kernels ----------------

__global__ void k_init() {
    int i = blockIdx.x * blockDim.x + threadIdx.x;
    if (i < H) g_attn_applied[i] = 0.f;
    if (i < L) g_score_c[i] = 0.f;
}

// attn_logits[m] = [emb0, h0] . W_attn_w[m] + b_attn_w[m]
__global__ void k_attn_logits(const int* __restrict__ din_p,
                              const float* __restrict__ emb,
                              const float* __restrict__ h0,
                              const float* __restrict__ Ww,
                              const float* __restrict__ bw) {
    int row  = (blockIdx.x * blockDim.x + threadIdx.x) >> 5;
    int lane = threadIdx.x & 31;
    if (row >= ML) return;
    const float4* w4 = (const float4*)(Ww + (size_t)row * (2 * H));
    const float4* e4 = (const float4*)(emb + (size_t)din_p[0] * H);
    const float4* h4 = (const float4*)h0;
    float acc = 0.f;
    #pragma unroll
    for (int q = lane; q < 256; q += 32) {
        float4 a = w4[q]; float4 x = e4[q];
        acc += a.x * x.x + a.y * x.y + a.z * x.z + a.w * x.w;
    }
    #pragma unroll
    for (int q = lane; q < 256; q += 32) {
        float4 a = w4[256 + q]; float4 x = h4[q];
        acc += a.x * x.x + a.y * x.y + a.z * x.z + a.w * x.w;
    }
    acc = warp_reduce_sum(acc);
    if (lane == 0) g_attn_logits[row] = acc + bw[row];
}

// fused softmax(ML) + attn_applied
__global__ void k_attn_applied(const float* __restrict__ E) {
    __shared__ float sred[32];
    __shared__ float w[16];
    int t = threadIdx.x;
    float a = g_attn_logits[t];
    float b = g_attn_logits[t + 1024];
    float m = block_reduce_max(fmaxf(a, b), sred);
    float s = block_reduce_sum(expf(a - m) + expf(b - m), sred);
    float inv = 1.f / s;
    int r0 = blockIdx.x * 16;
    if (t < 16) w[t] = expf(g_attn_logits[r0 + t] - m) * inv;
    __syncthreads();
    float acc = 0.f;
    #pragma unroll
    for (int i = 0; i < 16; i++)
        acc += w[i] * E[(size_t)(r0 + i) * H + t];
    atomicAdd(&g_attn_applied[t], acc);
}

// rnn_in[j] = relu([emb0, attn_applied] . W_attn_u[j] + b_attn_u[j])
__global__ void k_rnn_in(const int* __restrict__ din_p,
                         const float* __restrict__ emb,
                         const float* __restrict__ Wu,
                         const float* __restrict__ bu) {
    int row  = (blockIdx.x * blockDim.x + threadIdx.x) >> 5;
    int lane = threadIdx.x & 31;
    if (row >= H) return;
    const float4* w4 = (const float4*)(Wu + (size_t)row * (2 * H));
    const float4* e4 = (const float4*)(emb + (size_t)din_p[0] * H);
    const float4* a4 = (const float4*)g_attn_applied;
    float acc = 0.f;
    #pragma unroll
    for (int q = lane; q < 256; q += 32) {
        float4 a = w4[q]; float4 x = e4[q];
        acc += a.x * x.x + a.y * x.y + a.z * x.z + a.w * x.w;
    }
    #pragma unroll
    for (int q = lane; q < 256; q += 32) {
        float4 a = w4[256 + q]; float4 x = a4[q];
        acc += a.x * x.x + a.y * x.y + a.z * x.z + a.w * x.w;
    }
    acc = warp_reduce_sum(acc);
    if (lane == 0) g_rnn_in[row] = fmaxf(acc + bu[row], 0.f);
}

// gh = W_hh @ h0 + b_hh  (forked early)
__global__ void k_gh(const float* __restrict__ Whh, const float* __restrict__ bhh,
                     const float* __restrict__ h0) {
    int g    = (blockIdx.x * blockDim.x + threadIdx.x) >> 5;
    int lane = threadIdx.x & 31;
    if (g >= 3 * H) return;
    const float4* w4 = (const float4*)(Whh + (size_t)g * H);
    const float4* x4 = (const float4*)h0;
    float acc = 0.f;
    #pragma unroll
    for (int q = lane; q < 256; q += 32) {
        float4 a = w4[q]; float4 x = x4[q];
        acc += a.x * x.x + a.y * x.y + a.z * x.z + a.w * x.w;
    }
    acc = warp_reduce_sum(acc);
    if (lane == 0) g_gh[g] = acc + bhh[g];
}

// gi = W_ih @ rnn_in + b_ih
__global__ void k_gi(const float* __restrict__ Wih, const float* __restrict__ bih) {
    int g    = (blockIdx.x * blockDim.x + threadIdx.x) >> 5;
    int lane = threadIdx.x & 31;
    if (g >= 3 * H) return;
    const float4* w4 = (const float4*)(Wih + (size_t)g * H);
    const float4* x4 = (const float4*)g_rnn_in;
    float acc = 0.f;
    #pragma unroll
    for (int q = lane; q < 256; q += 32) {
        float4 a = w4[q]; float4 x = x4[q];
        acc += a.x * x.x + a.y * x.y + a.z * x.z + a.w * x.w;
    }
    acc = warp_reduce_sum(acc);
    if (lane == 0) g_gi[g] = acc + bih[g];
}

// GRU combine; writes h_new and final_hidden
__global__ void k_gru(const float* __restrict__ h0, float* __restrict__ out) {
    int t = threadIdx.x;
    float r = 1.f / (1.f + expf(-(g_gi[t] + g_gh[t])));
    float z = 1.f / (1.f + expf(-(g_gi[H + t] + g_gh[H + t])));
    float n = tanhf(g_gi[2 * H + t] + r * g_gh[2 * H + t]);
    float h = (1.f - z) * n + z * h0[t];
    g_hnew[t] = h;
    out[V + t] = h;
}

// score_g[v] = h_new . W_gen[v] + b_gen[v]  — warp per row, 256-thr blocks (co-resident)
__global__ void k_score_g(const float* __restrict__ Wg, const float* __restrict__ bg) {
    int row  = (blockIdx.x * blockDim.x + threadIdx.x) >> 5;
    int lane = threadIdx.x & 31;
    if (row >= V) return;
    const float4* w4 = (const float4*)(Wg + (size_t)row * H);
    const float4* h4 = (const float4*)g_hnew;
    float acc = 0.f;
    #pragma unroll
    for (int q = lane; q < 256; q += 32) {
        float4 a = w4[q]; float4 x = h4[q];
        acc += a.x * x.x + a.y * x.y + a.z * x.z + a.w * x.w;
    }
    acc = warp_reduce_sum(acc);
    if (lane == 0) g_score_g[row] = acc + bg[row];
}

// score_c via split-bf16 tensor-core GEMM with IN-KERNEL fp32->hi/lo conversion.
// CTA tile 128x128, K-tile 32, 8 warps (2x4), warp tile 64x32, m16n8k16.
// Term-major MMA ordering (16 independent accumulators between dependent reuses).
#define SAB 40
__global__ __launch_bounds__(256) void k_score_c_mma(
    const float* __restrict__ A,     // E: 2048 x 1024 fp32
    const float* __restrict__ B,     // W_copy: 1024 x 1024 fp32
    const float* __restrict__ bias, const float* __restrict__ h0) {
    __shared__ __nv_bfloat16 sAh[128 * SAB], sAl[128 * SAB];
    __shared__ __nv_bfloat16 sBh[128 * SAB], sBl[128 * SAB];
    int tid  = threadIdx.x;
    int lane = tid & 31;
    int wid  = tid >> 5;
    int wm   = wid >> 2;
    int wn   = wid & 3;
    int rowBase = blockIdx.y * 128;
    int colBase = blockIdx.x * 128;

    float acc[4][4][4];
    #pragma unroll
    for (int mf = 0; mf < 4; mf++)
        #pragma unroll
        for (int nf = 0; nf < 4; nf++)
            #pragma unroll
            for (int r = 0; r < 4; r++) acc[mf][nf][r] = 0.f;

    // loader mapping: thread -> (row, half-row of 16 floats)
    int lrow  = tid >> 1;      // 0..127
    int lhalf = tid & 1;       // 0..1

    const float4* A4 = (const float4*)A;  // row stride 256 float4
    const float4* B4 = (const float4*)B;

    float4 fa[4], fb[4];
    // LDG tile 0
    #pragma unroll
    for (int q = 0; q < 4; q++) {
        fa[q] = A4[(size_t)(rowBase + lrow) * 256 + lhalf * 4 + q];
        fb[q] = B4[(size_t)(colBase + lrow) * 256 + lhalf * 4 + q];
    }

    for (int kt = 0; kt < 1024; kt += 32) {
        // convert + STS current tile
        {
            int c = lhalf * 16;
            *(uint4*)&sAh[lrow * SAB + c]     = pack_hi8(fa[0], fa[1]);
            *(uint4*)&sAh[lrow * SAB + c + 8] = pack_hi8(fa[2], fa[3]);
            *(uint4*)&sAl[lrow * SAB + c]     = pack_lo8(fa[0], fa[1]);
            *(uint4*)&sAl[lrow * SAB + c + 8] = pack_lo8(fa[2], fa[3]);
            *(uint4*)&sBh[lrow * SAB + c]     = pack_hi8(fb[0], fb[1]);
            *(uint4*)&sBh[lrow * SAB + c + 8] = pack_hi8(fb[2], fb[3]);
            *(uint4*)&sBl[lrow * SAB + c]     = pack_lo8(fb[0], fb[1]);
            *(uint4*)&sBl[lrow * SAB + c + 8] = pack_lo8(fb[2], fb[3]);
        }
        __syncthreads();
        // LDG next tile (hidden under MMAs)
        if (kt + 32 < 1024) {
            int kq = (kt + 32) >> 2;
            #pragma unroll
            for (int q = 0; q < 4; q++) {
                fa[q] = A4[(size_t)(rowBase + lrow) * 256 + kq + lhalf * 4 + q];
                fb[q] = B4[(size_t)(colBase + lrow) * 256 + kq + lhalf * 4 + q];
            }
        }
        #pragma unroll
        for (int ks = 0; ks < 2; ks++) {
            int kk = ks * 16;
            uint32_t ah[4][4], al[4][4];
            int arow = wm * 64 + (lane & 15);
            int akc  = kk + ((lane >> 4) & 1) * 8;
            #pragma unroll
            for (int mf = 0; mf < 4; mf++) {
                ldsm_x4(ah[mf], smem_u32(&sAh[(arow + mf * 16) * SAB + akc]));
                ldsm_x4(al[mf], smem_u32(&sAl[(arow + mf * 16) * SAB + akc]));
            }
            // B: all 4 nf 8x8 matrices per k-half in one ldmatrix.x4
            uint32_t bh0[4], bh1[4], bl0[4], bl1[4];
            int brow = wn * 32 + lane;
            ldsm_x4(bh0, smem_u32(&sBh[brow * SAB + kk]));
            ldsm_x4(bh1, smem_u32(&sBh[brow * SAB + kk + 8]));
            ldsm_x4(bl0, smem_u32(&sBl[brow * SAB + kk]));
            ldsm_x4(bl1, smem_u32(&sBl[brow * SAB + kk + 8]));
            // term-major: 16 independent MMAs per term
            #pragma unroll
            for (int mf = 0; mf < 4; mf++)
                #pragma unroll
                for (int nf = 0; nf < 4; nf++)
                    mma_bf16(acc[mf][nf], ah[mf], bh0[nf], bh1[nf]);
            #pragma unroll
            for (int mf = 0; mf < 4; mf++)
                #pragma unroll
                for (int nf = 0; nf < 4; nf++)
                    mma_bf16(acc[mf][nf], ah[mf], bl0[nf], bl1[nf]);
            #pragma unroll
            for (int mf = 0; mf < 4; mf++)
                #pragma unroll
                for (int nf = 0; nf < 4; nf++)
                    mma_bf16(acc[mf][nf], al[mf], bh0[nf], bh1[nf]);
        }
        __syncthreads();
    }

    // epilogue: tanh + h0-weighted reduce over j; per-row atomicAdd
    int g   = lane >> 2;
    int tig = lane & 3;
    float bj[4][2], hj[4][2];
    #pragma unroll
    for (int nf = 0; nf < 4; nf++) {
        int j0 = colBase + wn * 32 + nf * 8 + tig * 2;
        bj[nf][0] = bias[j0];     bj[nf][1] = bias[j0 + 1];
        hj[nf][0] = h0[j0];       hj[nf][1] = h0[j0 + 1];
    }
    #pragma unroll
    for (int mf = 0; mf < 4; mf++) {
        float s0 = 0.f, s1 = 0.f;
        #pragma unroll
        for (int nf = 0; nf < 4; nf++) {
            s0 += tanhf(acc[mf][nf][0] + bj[nf][0]) * hj[nf][0]
                + tanhf(acc[mf][nf][1] + bj[nf][1]) * hj[nf][1];
            s1 += tanhf(acc[mf][nf][2] + bj[nf][0]) * hj[nf][0]
                + tanhf(acc[mf][nf][3] + bj[nf][1]) * hj[nf][1];
        }
        s0 += __shfl_xor_sync(0xffffffffu, s0, 1);
        s0 += __shfl_xor_sync(0xffffffffu, s0, 2);
        s1 += __shfl_xor_sync(0xffffffffu, s1, 1);
        s1 += __shfl_xor_sync(0xffffffffu, s1, 2);
        if (tig == 0) {
            int r = rowBase + wm * 64 + mf * 16 + g;
            atomicAdd(&g_score_c[r], s0);
            atomicAdd(&g_score_c[r + 8], s1);
        }
    }
}

// single-pass per-block (max, local expsum) over concat(score_g, score_c)
__global__ void k_redpass() {
    __shared__ float sred[32];
    int x = blockIdx.x * blockDim.x + threadIdx.x;
    float v = -1e30f;
    bool valid = (x < V + L);
    if (valid) v = (x < V) ? g_score_g[x] : g_score_c[x - V];
    float m = block_reduce_max(v, sred);
    float s = valid ? expf(v - m) : 0.f;
    s = block_reduce_sum(s, sred);
    if (threadIdx.x == 0) { g_bmax[blockIdx.x] = m; g_bsum[blockIdx.x] = s; }
}

__global__ void k_redfin() {
    __shared__ float sm[64], ss[64];
    int t = threadIdx.x;
    float m = (t < NRED) ? g_bmax[t] : -1e30f;
    sm[t] = m;
    __syncthreads();
    for (int o = 32; o; o >>= 1) { if (t < o) sm[t] = fmaxf(sm[t], sm[t + o]); __syncthreads(); }
    float M = sm[0];
    float s = (t < NRED) ? g_bsum[t] * expf(g_bmax[t] - M) : 0.f;
    ss[t] = s;
    __syncthreads();
    for (int o = 32; o; o >>= 1) { if (t < o) ss[t] += ss[t + o]; __syncthreads(); }
    if (t == 0) { g_smax = M; g_sinv = 1.f / ss[0]; }
}

// final_output[v] = prob_g[v]; zero final_weights region
__global__ void k_out_g(float* __restrict__ out) {
    int i = blockIdx.x * blockDim.x + threadIdx.x;
    if (i < H) out[V + H + i] = 0.f;
    if (i >= V) return;
    out[i] = expf(g_score_g[i] - g_smax) * g_sinv;
}

// prob_c scatter-add; matched rows directly into final_weights
__global__ void k_out_c(const int* __restrict__ iv, const int* __restrict__ din_p,
                        const float* __restrict__ E, float* __restrict__ out) {
    int i = blockIdx.x * blockDim.x + threadIdx.x;
    if (i >= L) return;
    float pc = expf(g_score_c[i] - g_smax) * g_sinv;
    int id = iv[i];
    atomicAdd(&out[id], pc);
    if (id == din_p[0]) {
        const float* Er = E + (size_t)i * H;
        float* fw = out + V + H;
        for (int j = 0; j < H; j++) atomicAdd(&fw[j], pc * Er[j]);
    }
}

// ---------------- launcher ----------------
extern "C" void kernel_launch(void* const* d_in, const int* in_sizes, int n_in,
                              void* d_out, int out_size) {
    const int*   din  = (const int*)d_in[0];
    const float* h0   = (const float*)d_in[1];
    const float* E    = (const float*)d_in[2];
    const int*   iv   = (const int*)d_in[3];
    const float* emb  = (const float*)d_in[4];
    const float* Ww   = (const float*)d_in[5];
    const float* bw   = (const float*)d_in[6];
    const float* Wu   = (const float*)d_in[7];
    const float* bu   = (const float*)d_in[8];
    const float* Wih  = (const float*)d_in[9];
    const float* bih  = (const float*)d_in[10];
    const float* Whh  = (const float*)d_in[11];
    const float* bhh  = (const float*)d_in[12];
    const float* Wc   = (const float*)d_in[13];
    const float* bc   = (const float*)d_in[14];
    const float* Wg   = (const float*)d_in[15];
    const float* bg   = (const float*)d_in[16];
    float* out = (float*)d_out;

    static cudaStream_t s2 = nullptr, s3 = nullptr;
    static cudaEvent_t evF0 = nullptr, evF1 = nullptr, evGh = nullptr, evJoin = nullptr;
    if (s2 == nullptr) {
        cudaStreamCreateWithFlags(&s2, cudaStreamNonBlocking);
        cudaStreamCreateWithFlags(&s3, cudaStreamNonBlocking);
        cudaEventCreateWithFlags(&evF0, cudaEventDisableTiming);
        cudaEventCreateWithFlags(&evF1, cudaEventDisableTiming);
        cudaEventCreateWithFlags(&evGh, cudaEventDisableTiming);
        cudaEventCreateWithFlags(&evJoin, cudaEventDisableTiming);
    }

    // fork gh (input-only deps) onto s3 immediately
    cudaEventRecord(evF0, 0);
    cudaStreamWaitEvent(s3, evF0, 0);
    k_gh<<<(3 * H * 32) / 256, 256, 0, s3>>>(Whh, bhh, h0);
    cudaEventRecord(evGh, s3);

    k_init<<<8, 256>>>();

    // fork score_c MMA (with fused split) onto s2
    cudaEventRecord(evF1, 0);
    cudaStreamWaitEvent(s2, evF1, 0);
    {
        dim3 grid(H / 128, L / 128);  // (8, 16)
        k_score_c_mma<<<grid, 256, 0, s2>>>(E, Wc, bc, h0);
    }
    cudaEventRecord(evJoin, s2);

    // main chain
    k_attn_logits<<<(ML * 32) / 256, 256>>>(din, emb, h0, Ww, bw);
    k_attn_applied<<<128, 1024>>>(E);
    k_rnn_in<<<(H * 32) / 256, 256>>>(din, emb, Wu, bu);
    k_gi<<<(3 * H * 32) / 256, 256>>>(Wih, bih);
    cudaStreamWaitEvent(0, evGh, 0);
    k_gru<<<1, 1024>>>(h0, out);
    k_score_g<<<(V + 7) / 8, 256>>>(Wg, bg);

    // join + tail
    cudaStreamWaitEvent(0, evJoin, 0);
    k_redpass<<<NRED, 1024>>>();
    k_redfin<<<1, 64>>>();
    k_out_g<<<(V + 255) / 256, 256>>>(out);
    k_out_c<<<L / 256, 256>>>(iv, din, E, out);
}